// round 15
// baseline (speedup 1.0000x reference)
#include <cuda_runtime.h>
#include <math.h>

typedef long long LL;

#define LAYERS 4
#define DM     1024
#define NH     16
#define FF     4096
#define VOC    32000
#define HD     64
#define BB     2
#define SS     2048
#define NT     (BB*SS)

// ---------------- scratch (static device globals; no allocation) ----------------
// fp32 buffers
__device__ float g_h  [NT*DM];
__device__ float g_tmp[NT*DM];
__device__ float g_v  [NT*DM];
__device__ float g_scores[(size_t)BB*NH*SS*SS];
// packed hi/lo bf16 pair buffers (uint2 per 2 fp32 elems = same bytes)
__device__ uint2 g_hp  [NT*DM/2];
__device__ uint2 g_qp  [NT*DM/2];
__device__ uint2 g_kp  [NT*DM/2];
__device__ uint2 g_vp  [NT*DM/2];
__device__ uint2 g_ctxp[NT*DM/2];
__device__ uint2 g_hnp [NT*DM/2];
__device__ uint2 g_ffnp[NT*FF/2];
// packed weights
__device__ uint2 g_wqp[LAYERS*DM*DM/2];
__device__ uint2 g_wkp[LAYERS*DM*DM/2];
__device__ uint2 g_wvp[LAYERS*DM*DM/2];
__device__ uint2 g_wop[LAYERS*DM*DM/2];
__device__ uint2 g_w1p[LAYERS*DM*FF/2];
__device__ uint2 g_w2p[LAYERS*DM*FF/2];
__device__ uint2 g_lmhp[(size_t)DM*VOC/2];

__device__ __forceinline__ float gelu_exact(float x) {
    return 0.5f * x * (1.0f + erff(x * 0.70710678118654752f));
}

__device__ __forceinline__ void cp16(void* s, const void* g) {
    unsigned sa = (unsigned)__cvta_generic_to_shared(s);
    asm volatile("cp.async.cg.shared.global [%0], [%1], 16;\n" :: "r"(sa), "l"(g));
}
__device__ __forceinline__ void cp_commit() { asm volatile("cp.async.commit_group;\n"); }
__device__ __forceinline__ void cp_wait0()  { asm volatile("cp.async.wait_group 0;\n"); }

// split packed pair (x0,x1) into bf16x2 hi and bf16x2 lo (lo = x - hi)
__device__ __forceinline__ void bf16x2_split(float x0, float x1, unsigned& hi, unsigned& lo) {
    asm("cvt.rn.bf16x2.f32 %0, %1, %2;\n" : "=r"(hi) : "f"(x1), "f"(x0));
    float h0 = __uint_as_float(hi << 16);
    float h1 = __uint_as_float(hi & 0xffff0000u);
    float l0 = x0 - h0;
    float l1 = x1 - h1;
    asm("cvt.rn.bf16x2.f32 %0, %1, %2;\n" : "=r"(lo) : "f"(l1), "f"(l0));
}

__device__ __forceinline__ void mma_bf16(float c[4], const unsigned a[4], const unsigned b[2]) {
    asm volatile(
        "mma.sync.aligned.m16n8k16.row.col.f32.bf16.bf16.f32 "
        "{%0,%1,%2,%3}, {%4,%5,%6,%7}, {%8,%9}, {%0,%1,%2,%3};\n"
        : "+f"(c[0]), "+f"(c[1]), "+f"(c[2]), "+f"(c[3])
        : "r"(a[0]), "r"(a[1]), "r"(a[2]), "r"(a[3]), "r"(b[0]), "r"(b[1]));
}

// ---------------- pre-split 3xBF16 tensor-core GEMM ----------------
// All operands pre-packed: per k-pair one uint2 {bf16x2 hi, bf16x2 lo}.
// A: [M][K/2] uint2 (k-pairs along rows). TRANSB: B [N][K/2] ; else B [K/2][N].
// OUT: 0 = fp32 C (ldc in floats), 1 = packed C (ldc in uint2, pairs along N).
template<int BM, int BN, int BK, int WM, int WN, bool TRANSB, int ACT, int OUT>
__global__ void __launch_bounds__(256)
pgemm(const uint2* __restrict__ A, const uint2* __restrict__ B,
      const float* __restrict__ bias, void* __restrict__ Cv,
      int K, int ldap, int ldbp, int ldc, float alpha,
      int Hdiv, LL sAb, LL sAh, LL sBb, LL sBh, LL sCb, LL sCh)
{
    constexpr int WARPS_M = BM / WM;
    constexpr int WARPS_N = BN / WN;
    constexpr int NTH = WARPS_M * WARPS_N * 32;
    constexpr int MT  = WM / 16;
    constexpr int NTt = WN / 8;
    constexpr int KP  = BK / 2;          // k-pairs per tile (8)
    constexpr int SA  = KP + 4;          // 12: conflict-free (≡4 mod 8)
    constexpr int SBt = KP + 4;          // 12
    constexpr int SBn = BN + 4;          // ≡4 mod 8 for BN=64/128
    constexpr int ASZ = BM * SA;
    constexpr int BSZ = TRANSB ? (BN * SBt) : (KP * SBn);

    __shared__ uint2 smA[2 * ASZ];
    __shared__ uint2 smB[2 * BSZ];

    const int z  = blockIdx.z;
    const int zb = z / Hdiv, zh = z % Hdiv;
    A += zb * sAb + zh * sAh;
    B += zb * sBb + zh * sBh;

    const int m0  = blockIdx.y * BM;
    const int n0  = blockIdx.x * BN;
    const int tid = threadIdx.x;
    const int warp = tid >> 5;
    const int lane = tid & 31;
    const int gr  = lane >> 2;
    const int tg  = lane & 3;
    const int wm0 = (warp / WARPS_N) * WM;
    const int wn0 = (warp % WARPS_N) * WN;

    float acc[MT][NTt][4];
#pragma unroll
    for (int i = 0; i < MT; i++)
#pragma unroll
        for (int j = 0; j < NTt; j++)
#pragma unroll
            for (int q = 0; q < 4; q++) acc[i][j][q] = 0.0f;

    auto loadTiles = [&](int kt, int buf) {
        const int k2 = kt * KP;
        uint2* Asp = smA + buf * ASZ;
        uint2* Bsp = smB + buf * BSZ;
#pragma unroll
        for (int r = 0; r < (BM * KP / 2) / NTH; r++) {
            int idx = r * NTH + tid;
            int m = idx / (KP / 2), c2 = idx % (KP / 2);
            cp16(&Asp[m * SA + c2 * 2], &A[(LL)(m0 + m) * ldap + k2 + c2 * 2]);
        }
        if (TRANSB) {
#pragma unroll
            for (int r = 0; r < (BN * KP / 2) / NTH; r++) {
                int idx = r * NTH + tid;
                int n = idx / (KP / 2), c2 = idx % (KP / 2);
                cp16(&Bsp[n * SBt + c2 * 2], &B[(LL)(n0 + n) * ldbp + k2 + c2 * 2]);
            }
        } else {
#pragma unroll
            for (int r = 0; r < (KP * BN / 2) / NTH; r++) {
                int idx = r * NTH + tid;
                int kp = idx / (BN / 2), c2 = idx % (BN / 2);
                cp16(&Bsp[kp * SBn + c2 * 2], &B[(LL)(k2 + kp) * ldbp + n0 + c2 * 2]);
            }
        }
        cp_commit();
    };

    auto compute = [&](int buf) {
        const uint2* Asp = smA + buf * ASZ;
        const uint2* Bsp = smB + buf * BSZ;
        // BK=16 -> one m16n8k16 step per tile
        unsigned ah[MT][4], al[MT][4], bh[NTt][2], bl[NTt][2];
#pragma unroll
        for (int mt = 0; mt < MT; mt++) {
            int b0 = (wm0 + mt * 16 + gr) * SA;
            uint2 p0 = Asp[b0 + tg];
            uint2 p1 = Asp[b0 + 8 * SA + tg];
            uint2 p2 = Asp[b0 + tg + 4];
            uint2 p3 = Asp[b0 + 8 * SA + tg + 4];
            ah[mt][0] = p0.x; al[mt][0] = p0.y;
            ah[mt][1] = p1.x; al[mt][1] = p1.y;
            ah[mt][2] = p2.x; al[mt][2] = p2.y;
            ah[mt][3] = p3.x; al[mt][3] = p3.y;
        }
#pragma unroll
        for (int nt = 0; nt < NTt; nt++) {
            int n = wn0 + nt * 8 + gr;
            uint2 q0, q1;
            if (TRANSB) {
                q0 = Bsp[n * SBt + tg];
                q1 = Bsp[n * SBt + tg + 4];
            } else {
                q0 = Bsp[tg * SBn + n];
                q1 = Bsp[(tg + 4) * SBn + n];
            }
            bh[nt][0] = q0.x; bl[nt][0] = q0.y;
            bh[nt][1] = q1.x; bl[nt][1] = q1.y;
        }
#pragma unroll
        for (int mt = 0; mt < MT; mt++)
#pragma unroll
            for (int nt = 0; nt < NTt; nt++) {
                mma_bf16(acc[mt][nt], ah[mt], bl[nt]);
                mma_bf16(acc[mt][nt], al[mt], bh[nt]);
                mma_bf16(acc[mt][nt], ah[mt], bh[nt]);
            }
    };

    const int KT = K / BK;
    loadTiles(0, 0);
    for (int kt = 0; kt < KT; kt++) {
        cp_wait0();
        __syncthreads();
        if (kt + 1 < KT) loadTiles(kt + 1, (kt + 1) & 1);
        compute(kt & 1);
        __syncthreads();
    }

    // epilogue
    float*  Cf = (float*)Cv + zb * sCb + zh * sCh;
    uint2*  Cp = (uint2*)Cv + zb * sCb + zh * sCh;
#pragma unroll
    for (int mt = 0; mt < MT; mt++) {
        int r0 = m0 + wm0 + mt * 16 + gr;
#pragma unroll
        for (int nt = 0; nt < NTt; nt++) {
            int cc = n0 + wn0 + nt * 8 + tg * 2;
            float v0 = acc[mt][nt][0] * alpha;
            float v1 = acc[mt][nt][1] * alpha;
            float v2 = acc[mt][nt][2] * alpha;
            float v3 = acc[mt][nt][3] * alpha;
            if (bias) {
                float b0 = bias[cc], b1 = bias[cc + 1];
                v0 += b0; v1 += b1; v2 += b0; v3 += b1;
            }
            if (ACT == 1) {
                v0 = gelu_exact(v0); v1 = gelu_exact(v1);
                v2 = gelu_exact(v2); v3 = gelu_exact(v3);
            }
            if (OUT == 0) {
                float2 p0 = {v0, v1};
                float2 p1 = {v2, v3};
                *reinterpret_cast<float2*>(&Cf[(LL)r0 * ldc + cc]) = p0;
                *reinterpret_cast<float2*>(&Cf[(LL)(r0 + 8) * ldc + cc]) = p1;
            } else {
                int pc = cc >> 1;
                unsigned h0, l0, h1, l1;
                bf16x2_split(v0, v1, h0, l0);
                bf16x2_split(v2, v3, h1, l1);
                uint2 u0 = {h0, l0};
                uint2 u1 = {h1, l1};
                Cp[(LL)r0 * ldc + pc] = u0;
                Cp[(LL)(r0 + 8) * ldc + pc] = u1;
            }
        }
    }
}

// ---------------- pack rows: out[rp][c] = packpair(in[2rp][c], in[2rp+1][c]) ----------------
__global__ void pack_rows_k(const float* __restrict__ in, uint2* __restrict__ out, int C)
{
    LL idx = (LL)blockIdx.x * 256 + threadIdx.x;
    LL rp = idx / C;
    int c  = (int)(idx % C);
    float a = in[(2 * rp) * C + c];
    float b = in[(2 * rp + 1) * C + c];
    unsigned hi, lo;
    bf16x2_split(a, b, hi, lo);
    uint2 u = {hi, lo};
    out[idx] = u;
}

// ---------------- softmax over rows of length 2048, packed output in place ----------------
__global__ void softmax2048_k(float* __restrict__ sc)
{
    __shared__ float red[32];
    float2* pf = (float2*)(sc + (LL)blockIdx.x * 2048);
    const int tid = threadIdx.x;
    float2 f[4];
    float mx = -1e30f;
#pragma unroll
    for (int i = 0; i < 4; i++) {
        f[i] = pf[tid + i * 256];
        mx = fmaxf(mx, fmaxf(f[i].x, f[i].y));
    }
#pragma unroll
    for (int o = 16; o > 0; o >>= 1) mx = fmaxf(mx, __shfl_xor_sync(0xffffffffu, mx, o));
    if ((tid & 31) == 0) red[tid >> 5] = mx;
    __syncthreads();
    if (tid < 32) {
        float t = (tid < 8) ? red[tid] : -1e30f;
#pragma unroll
        for (int o = 4; o > 0; o >>= 1) t = fmaxf(t, __shfl_xor_sync(0xffffffffu, t, o));
        if (tid == 0) red[0] = t;
    }
    __syncthreads();
    mx = red[0];
    __syncthreads();

    float s = 0.0f;
#pragma unroll
    for (int i = 0; i < 4; i++) {
        f[i].x = __expf(f[i].x - mx);
        f[i].y = __expf(f[i].y - mx);
        s += f[i].x + f[i].y;
    }
#pragma unroll
    for (int o = 16; o > 0; o >>= 1) s += __shfl_xor_sync(0xffffffffu, s, o);
    if ((tid & 31) == 0) red[tid >> 5] = s;
    __syncthreads();
    if (tid < 32) {
        float t = (tid < 8) ? red[tid] : 0.0f;
#pragma unroll
        for (int o = 4; o > 0; o >>= 1) t += __shfl_xor_sync(0xffffffffu, t, o);
        if (tid == 0) red[0] = t;
    }
    __syncthreads();
    float inv = 1.0f / red[0];
    uint2* pu = (uint2*)pf;
#pragma unroll
    for (int i = 0; i < 4; i++) {
        unsigned hi, lo;
        bf16x2_split(f[i].x * inv, f[i].y * inv, hi, lo);
        uint2 u = {hi, lo};
        pu[tid + i * 256] = u;
    }
}

// ---------------- residual add + layernorm (fp32 out + packed out) ----------------
__global__ void add_ln_k(const float* __restrict__ x, const float* __restrict__ r,
                         const float* __restrict__ g, const float* __restrict__ b,
                         float* __restrict__ o, uint2* __restrict__ op)
{
    __shared__ float redS[8];
    __shared__ float redQ[8];
    const LL row = blockIdx.x;
    const float2* px = (const float2*)(x + row * DM);
    const float2* pr = r ? (const float2*)(r + row * DM) : nullptr;
    const int tid = threadIdx.x;
    float2 v[2];
    float s = 0.0f, sq = 0.0f;
#pragma unroll
    for (int i = 0; i < 2; i++) {
        float2 t = px[tid + i * 256];
        if (pr) { float2 rr = pr[tid + i * 256]; t.x += rr.x; t.y += rr.y; }
        v[i] = t;
        s += t.x + t.y;
        sq = fmaf(t.x, t.x, fmaf(t.y, t.y, sq));
    }
#pragma unroll
    for (int off = 16; off > 0; off >>= 1) {
        s  += __shfl_xor_sync(0xffffffffu, s,  off);
        sq += __shfl_xor_sync(0xffffffffu, sq, off);
    }
    if ((tid & 31) == 0) { redS[tid >> 5] = s; redQ[tid >> 5] = sq; }
    __syncthreads();
    if (tid < 32) {
        float ts = (tid < 8) ? redS[tid] : 0.0f;
        float tq = (tid < 8) ? redQ[tid] : 0.0f;
#pragma unroll
        for (int off = 4; off > 0; off >>= 1) {
            ts += __shfl_xor_sync(0xffffffffu, ts, off);
            tq += __shfl_xor_sync(0xffffffffu, tq, off);
        }
        if (tid == 0) { redS[0] = ts; redQ[0] = tq; }
    }
    __syncthreads();
    const float mean = redS[0] * (1.0f / DM);
    const float var  = redQ[0] * (1.0f / DM) - mean * mean;
    const float rstd = rsqrtf(var + 1e-5f);
    float2* po = (float2*)(o + row * DM);
    uint2* pp  = op + row * (DM / 2);
#pragma unroll
    for (int i = 0; i < 2; i++) {
        int p = tid + i * 256;
        int d = p * 2;
        float y0 = (v[i].x - mean) * rstd * g[d]     + b[d];
        float y1 = (v[i].y - mean) * rstd * g[d + 1] + b[d + 1];
        float2 f2 = {y0, y1};
        po[p] = f2;
        unsigned hi, lo;
        bf16x2_split(y0, y1, hi, lo);
        uint2 u = {hi, lo};
        pp[p] = u;
    }
}

// ---------------- embedding + positional (fp32 + packed) ----------------
__global__ void embed_k(const int* __restrict__ ids, const float* __restrict__ emb,
                        const float* __restrict__ pe, float* __restrict__ h,
                        uint2* __restrict__ hp)
{
    LL pidx = (LL)blockIdx.x * 256 + threadIdx.x;   // over NT*DM/2 pairs
    int t  = (int)(pidx / (DM / 2));
    int pd = (int)(pidx % (DM / 2));
    int d  = pd * 2;
    int sp = t & (SS - 1);
    const float2 e  = *(const float2*)&emb[(LL)ids[t] * DM + d];
    const float2 pp = *(const float2*)&pe[(LL)sp * DM + d];
    float x0 = 2.0f * e.x + pp.x;
    float x1 = 2.0f * e.y + pp.y;
    float2 f2 = {x0, x1};
    *(float2*)&h[pidx * 2] = f2;
    unsigned hi, lo;
    bf16x2_split(x0, x1, hi, lo);
    uint2 u = {hi, lo};
    hp[pidx] = u;
}

// ---------------- host driver ----------------
extern "C" void kernel_launch(void* const* d_in, const int* in_sizes, int n_in,
                              void* d_out, int out_size)
{
    (void)in_sizes; (void)n_in; (void)out_size;

    const int*   ids  = (const int*)  d_in[0];
    const float* emb  = (const float*)d_in[1];
    const float* pe   = (const float*)d_in[2];
    const float* wq   = (const float*)d_in[3];
    const float* bq   = (const float*)d_in[4];
    const float* wk   = (const float*)d_in[5];
    const float* bk   = (const float*)d_in[6];
    const float* wv   = (const float*)d_in[7];
    const float* bv   = (const float*)d_in[8];
    const float* wo   = (const float*)d_in[9];
    const float* bo   = (const float*)d_in[10];
    const float* ln1g = (const float*)d_in[11];
    const float* ln1b = (const float*)d_in[12];
    const float* w1   = (const float*)d_in[13];
    const float* b1   = (const float*)d_in[14];
    const float* w2   = (const float*)d_in[15];
    const float* b2   = (const float*)d_in[16];
    const float* ln2g = (const float*)d_in[17];
    const float* ln2b = (const float*)d_in[18];
    const float* lnfg = (const float*)d_in[19];
    const float* lnfb = (const float*)d_in[20];
    const float* lmh  = (const float*)d_in[21];
    float* out = (float*)d_out;

    float *h, *tmp, *v, *sc;
    uint2 *hp, *qp, *kp, *vp, *ctxp, *hnp, *ffnp;
    uint2 *wqp, *wkp, *wvp, *wop, *w1p, *w2p, *lmhp;
    cudaGetSymbolAddress((void**)&h,    g_h);
    cudaGetSymbolAddress((void**)&tmp,  g_tmp);
    cudaGetSymbolAddress((void**)&v,    g_v);
    cudaGetSymbolAddress((void**)&sc,   g_scores);
    cudaGetSymbolAddress((void**)&hp,   g_hp);
    cudaGetSymbolAddress((void**)&qp,   g_qp);
    cudaGetSymbolAddress((void**)&kp,   g_kp);
    cudaGetSymbolAddress((void**)&vp,   g_vp);
    cudaGetSymbolAddress((void**)&ctxp, g_ctxp);
    cudaGetSymbolAddress((void**)&hnp,  g_hnp);
    cudaGetSymbolAddress((void**)&ffnp, g_ffnp);
    cudaGetSymbolAddress((void**)&wqp,  g_wqp);
    cudaGetSymbolAddress((void**)&wkp,  g_wkp);
    cudaGetSymbolAddress((void**)&wvp,  g_wvp);
    cudaGetSymbolAddress((void**)&wop,  g_wop);
    cudaGetSymbolAddress((void**)&w1p,  g_w1p);
    cudaGetSymbolAddress((void**)&w2p,  g_w2p);
    cudaGetSymbolAddress((void**)&lmhp, g_lmhp);

    // pack all weights: rows paired along K
    pack_rows_k<<<(LAYERS * DM / 2) * DM / 256, 256>>>(wq, wqp, DM);
    pack_rows_k<<<(LAYERS * DM / 2) * DM / 256, 256>>>(wk, wkp, DM);
    pack_rows_k<<<(LAYERS * DM / 2) * DM / 256, 256>>>(wv, wvp, DM);
    pack_rows_k<<<(LAYERS * DM / 2) * DM / 256, 256>>>(wo, wop, DM);
    pack_rows_k<<<(LAYERS * DM / 2) * FF / 256, 256>>>(w1, w1p, FF);
    pack_rows_k<<<(LAYERS * FF / 2) * DM / 256, 256>>>(w2, w2p, DM);
    pack_rows_k<<<(DM / 2) * VOC / 256, 256>>>(lmh, lmhp, VOC);

    // h = 2*tok + pe (fp32 + packed)
    embed_k<<<(NT * DM / 2) / 256, 256>>>(ids, emb, pe, h, hp);

    const float scale = 1.0f / 8.0f;

    for (int i = 0; i < LAYERS; i++) {
        const uint2* wqi = wqp + (LL)i * DM * DM / 2;  const float* bqi = bq + (LL)i * DM;
        const uint2* wki = wkp + (LL)i * DM * DM / 2;  const float* bki = bk + (LL)i * DM;
        const uint2* wvi = wvp + (LL)i * DM * DM / 2;  const float* bvi = bv + (LL)i * DM;
        const uint2* woi = wop + (LL)i * DM * DM / 2;  const float* boi = bo + (LL)i * DM;
        const uint2* w1i = w1p + (LL)i * DM * FF / 2;  const float* b1i = b1 + (LL)i * FF;
        const uint2* w2i = w2p + (LL)i * FF * DM / 2;  const float* b2i = b2 + (LL)i * DM;

        // Q/K/V projections: A=hp [NT][DM/2], B=W [DM/2][DM]
        {
            dim3 grid(DM / 128, NT / 128, 1);
            pgemm<128,128,16,64,32,false,0,1><<<grid, 256>>>(hp, wqi, bqi, qp,
                DM, DM/2, DM, DM/2, 1.0f, 1, 0,0, 0,0, 0,0);
            pgemm<128,128,16,64,32,false,0,1><<<grid, 256>>>(hp, wki, bki, kp,
                DM, DM/2, DM, DM/2, 1.0f, 1, 0,0, 0,0, 0,0);
            pgemm<128,128,16,64,32,false,0,0><<<grid, 256>>>(hp, wvi, bvi, v,
                DM, DM/2, DM, DM,   1.0f, 1, 0,0, 0,0, 0,0);
        }

        // pack V along tokens for ctx GEMM B operand
        pack_rows_k<<<(NT / 2) * DM / 256, 256>>>(v, vp, DM);

        // scores[z] = scale * Qh @ Kh^T  (A packed, B packed-trans)
        {
            dim3 grid(SS / 128, SS / 128, BB * NH);
            pgemm<128,128,16,64,32,true,0,0><<<grid, 256>>>(
                qp, kp, nullptr, sc, HD, DM/2, DM/2, SS, scale,
                NH, (LL)SS * DM/2, HD/2, (LL)SS * DM/2, HD/2,
                (LL)NH * SS * SS, (LL)SS * SS);
        }

        // softmax rows (fp32 in, packed out, in place)
        softmax2048_k<<<BB * NH * SS, 256>>>(sc);

        // ctx[z] = P @ Vh -> packed ctx
        {
            dim3 grid(HD / 64, SS / 128, BB * NH);
            pgemm<128,64,16,32,32,false,0,1><<<grid, 256>>>(
                (const uint2*)sc, vp, nullptr, ctxp, SS, SS/2, DM, DM/2, 1.0f,
                NH, (LL)NH * SS * (SS/2), (LL)SS * (SS/2),
                (LL)(SS/2) * DM, (LL)HD, (LL)SS * (DM/2), (LL)(HD/2));
        }

        // attn_out = ctx @ wo + bo (fp32)
        {
            dim3 grid(DM / 128, NT / 128, 1);
            pgemm<128,128,16,64,32,false,0,0><<<grid, 256>>>(ctxp, woi, boi, tmp,
                DM, DM/2, DM, DM, 1.0f, 1, 0,0, 0,0, 0,0);
        }
        // h = LN(h + attn_out)  (fp32 h + packed hp)
        add_ln_k<<<NT, 256>>>(h, tmp, ln1g + (LL)i * DM, ln1b + (LL)i * DM, h, hp);

        // ffn1 = gelu(h @ w1 + b1) -> packed
        {
            dim3 grid(FF / 128, NT / 128, 1);
            pgemm<128,128,16,64,32,false,1,1><<<grid, 256>>>(hp, w1i, b1i, ffnp,
                DM, DM/2, FF, FF/2, 1.0f, 1, 0,0, 0,0, 0,0);
        }
        // ffn2 = ffn1 @ w2 + b2 (fp32)
        {
            dim3 grid(DM / 128, NT / 128, 1);
            pgemm<128,128,16,64,32,false,0,0><<<grid, 256>>>(ffnp, w2i, b2i, tmp,
                FF, FF/2, DM, DM, 1.0f, 1, 0,0, 0,0, 0,0);
        }
        // h = LN(h + ffn2)
        add_ln_k<<<NT, 256>>>(h, tmp, ln2g + (LL)i * DM, ln2b + (LL)i * DM, h, hp);
    }

    // final LN -> packed hn (fp32 side dumped to tmp)
    add_ln_k<<<NT, 256>>>(h, nullptr, lnfg, lnfb, tmp, hnp);

    // logits = hn @ lm_head (fp32 out)
    {
        dim3 grid(VOC / 128, NT / 128, 1);
        pgemm<128,128,16,64,32,false,0,0><<<grid, 256>>>(hnp, lmhp, nullptr, out,
            DM, DM/2, VOC, VOC, 1.0f, 1, 0,0, 0,0, 0,0);
    }
}